// round 16
// baseline (speedup 1.0000x reference)
#include <cuda_runtime.h>

#define B_TOT 8192
#define T_STEPS 256
#define SD 12          // state dim
#define AD 4           // action dim
#define DD 16          // D = SD + AD
#define HH 16          // hidden
#define GG 64          // 4*H

#define WPB 2                      // warps (= batches) per block
#define THREADS (WPB * 32)
#define NBLOCKS (B_TOT / WPB)

typedef unsigned long long ull;

// Per-lane packed weights. lane = hi*16 + j owns gate rows r0 (hi=0: i_j, hi=1: f_j)
// and r1 (hi=0: g_j, hi=1: o_j).
__device__ float2 g_WxL[32 * 16];
__device__ float2 g_WhL[32 * 16];
__device__ float4 g_SBL[32];                    // (S_r0, S_r1, B_r0, B_r1)
__device__ __align__(16) float2 g_WoL[SD * 8];  // W_out packed pairs, row-major
__device__ float  g_boL[SD];

__global__ void vm_prep(const float* __restrict__ ln_gamma,
                        const float* __restrict__ ln_beta,
                        const float* __restrict__ W_in,   // [H][D]
                        const float* __restrict__ b_in,   // [H]
                        const float* __restrict__ W_ih,   // [G][H]
                        const float* __restrict__ W_hh,   // [G][H]
                        const float* __restrict__ b_ih,
                        const float* __restrict__ b_hh,
                        const float* __restrict__ W_out,  // [SD][H]
                        const float* __restrict__ b_out)
{
    int r = threadIdx.x;   // gate row 0..63
    if (r < GG) {
        int j    = r & 15;
        int hi   = (r >> 4) & 1;
        int s    = r >> 5;
        int lane = hi * 16 + j;
        float wp[DD];
        float S = 0.f, bB = 0.f;
        for (int d = 0; d < DD; d++) {
            float acc = 0.f;
            for (int k = 0; k < HH; k++) acc += W_ih[r * HH + k] * W_in[k * DD + d];
            wp[d] = acc * ln_gamma[d];             // fold gamma
            bB += acc * ln_beta[d];                // fold beta
            S += wp[d];
        }
        float bi = 0.f;
        for (int k = 0; k < HH; k++) bi += W_ih[r * HH + k] * b_in[k];
        ((float*)&g_SBL[lane])[s]     = S;
        ((float*)&g_SBL[lane])[2 + s] = bB + bi + b_ih[r] + b_hh[r];
        for (int p = 0; p < 8; p++) {
            g_WxL[lane * 16 + s * 8 + p] = make_float2(wp[2 * p], wp[2 * p + 1]);
            g_WhL[lane * 16 + s * 8 + p] = make_float2(W_hh[r * HH + 2 * p],
                                                       W_hh[r * HH + 2 * p + 1]);
        }
    }
    if (r < SD) {
        for (int p = 0; p < 8; p++)
            g_WoL[r * 8 + p] = make_float2(W_out[r * HH + 2 * p], W_out[r * HH + 2 * p + 1]);
        g_boL[r] = b_out[r];
    }
}

__device__ __forceinline__ void fma2(ull& acc, ull w, ull x) {
    asm("fma.rn.f32x2 %0, %1, %2, %0;" : "+l"(acc) : "l"(w), "l"(x));
}
__device__ __forceinline__ void add2(ull& acc, ull x) {
    asm("add.rn.f32x2 %0, %0, %1;" : "+l"(acc) : "l"(x));
}
__device__ __forceinline__ ull mul2(ull a, ull b) {
    ull r; asm("mul.rn.f32x2 %0, %1, %2;" : "=l"(r) : "l"(a), "l"(b)); return r;
}
__device__ __forceinline__ float2 up(ull v) {
    float2 r; asm("mov.b64 {%0, %1}, %2;" : "=f"(r.x), "=f"(r.y) : "l"(v)); return r;
}
__device__ __forceinline__ ull pk(float lo, float hi_) {
    ull r; asm("mov.b64 %0, {%1, %2};" : "=l"(r) : "f"(lo), "f"(hi_)); return r;
}
__device__ __forceinline__ float ex2_(float x) {
    float r; asm("ex2.approx.f32 %0, %1;" : "=f"(r) : "f"(x)); return r;
}
__device__ __forceinline__ float rcp_(float x) {
    float r; asm("rcp.approx.f32 %0, %1;" : "=f"(r) : "f"(x)); return r;
}
__device__ __forceinline__ float sigm(float x) {
    return rcp_(1.f + ex2_(x * -1.44269504f));
}
__device__ __forceinline__ float tanh5(float x) {
    return fmaf(-2.f, rcp_(1.f + ex2_(x * 2.88539008f)), 1.f);
}

__global__ __launch_bounds__(THREADS, 9) void vm_main(
    const float* __restrict__ init_state,   // [B][1][SD]
    const float* __restrict__ commands,     // [B][T][AD]
    float* __restrict__ out)                // [B][T][SD]
{
    __shared__ __align__(16) float scmd[WPB][T_STEPS * AD];   // whole cmd sequence per warp
    __shared__ __align__(16) float xbuf[WPB][16];             // dims 0..11 used (state part)
    __shared__ __align__(16) float hbuf[WPB][16];
    __shared__ ulonglong2 sWo[SD * 5];   // stride-5 quads: <=2-way bank conflict
    __shared__ float sbo[SD];

    int tid  = threadIdx.x;
    int w    = tid >> 5;     // warp in block = local batch
    int lane = tid & 31;
    int j    = lane & 15;
    int hi   = lane >> 4;
    int b    = blockIdx.x * WPB + w;

    // stage W_out into padded smem
    {
        const ulonglong2* gq = (const ulonglong2*)g_WoL;
        for (int i = tid; i < SD * 4; i += THREADS)
            sWo[(i >> 2) * 5 + (i & 3)] = gq[i];
        for (int i = tid; i < SD; i += THREADS) sbo[i] = g_boL[i];
    }
    // stage this batch's entire command sequence (coalesced, once)
    {
        const float4* cf = (const float4*)(commands + (size_t)b * (T_STEPS * AD));
        float4* sf = (float4*)scmd[w];
        #pragma unroll
        for (int i = 0; i < (T_STEPS * AD) / (4 * 32); i++)
            sf[lane + 32 * i] = cf[lane + 32 * i];
    }

    // loop-invariant gate weights in registers
    ull Wx[16], Wh[16];
    const ull* wx = (const ull*)g_WxL + lane * 16;
    const ull* wh = (const ull*)g_WhL + lane * 16;
    #pragma unroll
    for (int i = 0; i < 16; i++) { Wx[i] = wx[i]; Wh[i] = wh[i]; }
    float4 SB = g_SBL[lane];

    int  jw      = (j < SD) ? j : 0;
    bool stlane  = (hi == 0) && (j < SD);
    float kk     = hi ? -1.44269504f : 2.88539008f;   // sigm vs tanh exponent scale

    float st = 0.f;
    if (stlane) st = init_state[b * SD + j];
    float c = 0.f;

    float* outp = out + (size_t)b * (T_STEPS * SD);

    // x(0) state part + h(-1) = 0
    if (stlane)  xbuf[w][j] = st;
    if (hi == 0) hbuf[w][j] = 0.f;
    __syncthreads();   // sWo + scmd + xbuf + hbuf visible

    const ulonglong2* xq4 = (const ulonglong2*)xbuf[w];
    const ulonglong2* hq4 = (const ulonglong2*)hbuf[w];
    const ulonglong2* cq4 = (const ulonglong2*)scmd[w];
    const ulonglong2* wop = sWo + jw * 5 + 2 * hi;    // this half's 2 Wout quads (split-K)
    const ulonglong2* hsel = hq4 + 2 * hi;            // this half's 2 h quads for Wout
    // b_out folded into accumulator init. Each half contributes bo/2 after its
    // horizontal sum, so the combined (aos + aoo) adds exactly bo once.
    ull bo2 = pk(sbo[jw] * 0.25f, sbo[jw] * 0.25f);

    int  p16 = (j >= 1 && j <= 6) ? (j + ((j & 1) ? 1 : -1)) : j;
    bool isc = (j >= 1 && j <= 6);

    #pragma unroll 8
    for (int t = 0; t < T_STEPS; t++) {
        // ---- x/h loads: batched (MLP), x quad 3 comes straight from staged cmds ----
        ulonglong2 v0 = xq4[0], v1 = xq4[1], v2 = xq4[2];
        ulonglong2 v3 = cq4[t];                       // cmd(t): dims 12..15, broadcast
        ulonglong2 h0 = hq4[0], h1 = hq4[1], h2 = hq4[2], h3 = hq4[3];
        ull xp[8], hp[8];
        xp[0] = v0.x; xp[1] = v0.y; xp[2] = v1.x; xp[3] = v1.y;
        xp[4] = v2.x; xp[5] = v2.y; xp[6] = v3.x; xp[7] = v3.y;
        hp[0] = h0.x; hp[1] = h0.y; hp[2] = h1.x; hp[3] = h1.y;
        hp[4] = h2.x; hp[5] = h2.y; hp[6] = h3.x; hp[7] = h3.y;

        // ---- LN stats (two chains) ----
        ull sa = xp[0], sb2 = xp[1];
        ull qa = mul2(xp[0], xp[0]), qb = mul2(xp[1], xp[1]);
        #pragma unroll
        for (int d = 2; d < 8; d += 2) {
            add2(sa, xp[d]);      fma2(qa, xp[d],     xp[d]);
            add2(sb2, xp[d + 1]); fma2(qb, xp[d + 1], xp[d + 1]);
        }
        add2(sa, sb2); add2(qa, qb);
        float2 su = up(sa), qu = up(qa);
        float mu   = (su.x + su.y) * 0.0625f;
        float var  = fmaf(-mu, mu, (qu.x + qu.y) * 0.0625f);
        float rstd = rsqrtf(var + 1e-5f);

        // ---- gate dots: x part + h part (h(t-1)) ----
        ull a0x = mul2(Wx[0], xp[0]);
        ull a1x = mul2(Wx[8], xp[0]);
        ull a0h = mul2(Wh[0], hp[0]);
        ull a1h = mul2(Wh[8], hp[0]);
        #pragma unroll
        for (int d = 1; d < 8; d++) {
            fma2(a0x, Wx[d],     xp[d]);
            fma2(a1x, Wx[8 + d], xp[d]);
            fma2(a0h, Wh[d],     hp[d]);
            fma2(a1h, Wh[8 + d], hp[d]);
        }
        float2 u0 = up(a0x), u1 = up(a1x), w0h = up(a0h), w1h = up(a1h);
        float g0 = fmaf(rstd, fmaf(-mu, SB.x, u0.x + u0.y), SB.z) + (w0h.x + w0h.y);
        float g1 = fmaf(rstd, fmaf(-mu, SB.y, u1.x + u1.y), SB.w) + (w1h.x + w1h.y);

        // ---- activations: hi=0 -> (sig i, tanh g) ; hi=1 -> (sig f, sig o) ----
        float sA = sigm(g0);
        float r1 = rcp_(1.f + ex2_(g1 * kk));
        float v1a = hi ? r1 : fmaf(-2.f, r1, 1.f);
        float a  = sA * v1a;                              // sig(i)*tanh(g) on hi=0
        float send1 = hi ? sA : a;
        float fs = __shfl_xor_sync(0xffffffffu, send1, 16);  // hi=0 gets sig(f)
        float os = __shfl_xor_sync(0xffffffffu, v1a, 16);    // hi=0 gets sig(o)
        c = fmaf(fs, c, a);
        float h = os * tanh5(c);

        if (hi == 0) hbuf[w][j] = h;
        __syncwarp();

        // ---- Wout split-K: this half dots its 8 dims of h(t) ----
        ulonglong2 hs0 = hsel[0], hs1 = hsel[1];
        ulonglong2 wv0 = wop[0],  wv1 = wop[1];
        ull ao = bo2;
        fma2(ao, wv0.x, hs0.x); fma2(ao, wv0.y, hs0.y);
        fma2(ao, wv1.x, hs1.x); fma2(ao, wv1.y, hs1.y);
        float2 aof = up(ao);
        float aos = aof.x + aof.y;
        float aoo = __shfl_xor_sync(0xffffffffu, aos, 16);
        st = st + (aos + aoo);

        // ---- sincos renorm, branch-free ----
        float other = __shfl_sync(0xffffffffu, st, p16, 16);
        float rn = rsqrtf(fmaf(st, st, other * other));
        st = isc ? st * rn : st;

        if (stlane) { outp[t * SD + j] = st; xbuf[w][j] = st; }
        __syncwarp();
    }
}

extern "C" void kernel_launch(void* const* d_in, const int* in_sizes, int n_in,
                              void* d_out, int out_size) {
    const float* init_state = (const float*)d_in[0];
    const float* commands   = (const float*)d_in[1];
    const float* ln_gamma   = (const float*)d_in[2];
    const float* ln_beta    = (const float*)d_in[3];
    const float* W_in       = (const float*)d_in[4];
    const float* b_in       = (const float*)d_in[5];
    const float* W_ih       = (const float*)d_in[6];
    const float* W_hh       = (const float*)d_in[7];
    const float* b_ih       = (const float*)d_in[8];
    const float* b_hh       = (const float*)d_in[9];
    const float* W_out      = (const float*)d_in[10];
    const float* b_out      = (const float*)d_in[11];
    float* out = (float*)d_out;

    vm_prep<<<1, 64>>>(ln_gamma, ln_beta, W_in, b_in, W_ih, W_hh, b_ih, b_hh, W_out, b_out);
    vm_main<<<NBLOCKS, THREADS>>>(init_state, commands, out);
}

// round 17
// speedup vs baseline: 1.2373x; 1.2373x over previous
#include <cuda_runtime.h>

#define B_TOT 8192
#define T_STEPS 256
#define SD 12          // state dim
#define AD 4           // action dim
#define DD 16          // D = SD + AD
#define HH 16          // hidden
#define GG 64          // 4*H

#define WPB 2                      // warps (= batches) per block
#define THREADS (WPB * 32)
#define NBLOCKS (B_TOT / WPB)

typedef unsigned long long ull;

// Per-lane packed weights. lane = hi*16 + j owns gate rows r0 (hi=0: i_j, hi=1: f_j)
// and r1 (hi=0: g_j, hi=1: o_j).
__device__ float2 g_WxL[32 * 16];
__device__ float2 g_WhL[32 * 16];
__device__ float4 g_SBL[32];                    // (S_r0, S_r1, B_r0, B_r1)
__device__ __align__(16) float2 g_WoL[SD * 8];  // W_out packed pairs, row-major
__device__ float  g_boL[SD];

__global__ void vm_prep(const float* __restrict__ ln_gamma,
                        const float* __restrict__ ln_beta,
                        const float* __restrict__ W_in,   // [H][D]
                        const float* __restrict__ b_in,   // [H]
                        const float* __restrict__ W_ih,   // [G][H]
                        const float* __restrict__ W_hh,   // [G][H]
                        const float* __restrict__ b_ih,
                        const float* __restrict__ b_hh,
                        const float* __restrict__ W_out,  // [SD][H]
                        const float* __restrict__ b_out)
{
    int r = threadIdx.x;   // gate row 0..63
    if (r < GG) {
        int j    = r & 15;
        int hi   = (r >> 4) & 1;
        int s    = r >> 5;
        int lane = hi * 16 + j;
        float wp[DD];
        float S = 0.f, bB = 0.f;
        for (int d = 0; d < DD; d++) {
            float acc = 0.f;
            for (int k = 0; k < HH; k++) acc += W_ih[r * HH + k] * W_in[k * DD + d];
            wp[d] = acc * ln_gamma[d];             // fold gamma
            bB += acc * ln_beta[d];                // fold beta
            S += wp[d];
        }
        float bi = 0.f;
        for (int k = 0; k < HH; k++) bi += W_ih[r * HH + k] * b_in[k];
        ((float*)&g_SBL[lane])[s]     = S;
        ((float*)&g_SBL[lane])[2 + s] = bB + bi + b_ih[r] + b_hh[r];
        for (int p = 0; p < 8; p++) {
            g_WxL[lane * 16 + s * 8 + p] = make_float2(wp[2 * p], wp[2 * p + 1]);
            g_WhL[lane * 16 + s * 8 + p] = make_float2(W_hh[r * HH + 2 * p],
                                                       W_hh[r * HH + 2 * p + 1]);
        }
    }
    if (r < SD) {
        for (int p = 0; p < 8; p++)
            g_WoL[r * 8 + p] = make_float2(W_out[r * HH + 2 * p], W_out[r * HH + 2 * p + 1]);
        g_boL[r] = b_out[r];
    }
}

__device__ __forceinline__ void fma2(ull& acc, ull w, ull x) {
    asm("fma.rn.f32x2 %0, %1, %2, %0;" : "+l"(acc) : "l"(w), "l"(x));
}
__device__ __forceinline__ void add2(ull& acc, ull x) {
    asm("add.rn.f32x2 %0, %0, %1;" : "+l"(acc) : "l"(x));
}
__device__ __forceinline__ ull mul2(ull a, ull b) {
    ull r; asm("mul.rn.f32x2 %0, %1, %2;" : "=l"(r) : "l"(a), "l"(b)); return r;
}
__device__ __forceinline__ float2 up(ull v) {
    float2 r; asm("mov.b64 {%0, %1}, %2;" : "=f"(r.x), "=f"(r.y) : "l"(v)); return r;
}
__device__ __forceinline__ ull pk(float lo, float hi_) {
    ull r; asm("mov.b64 %0, {%1, %2};" : "=l"(r) : "f"(lo), "f"(hi_)); return r;
}
// hardware tanh (sm_75+): single MUFU op, ~1e-5 abs err
__device__ __forceinline__ float tanh_(float x) {
    float r; asm("tanh.approx.f32 %0, %1;" : "=f"(r) : "f"(x)); return r;
}

__global__ __launch_bounds__(THREADS, 8) void vm_main(
    const float* __restrict__ init_state,   // [B][1][SD]
    const float* __restrict__ commands,     // [B][T][AD]
    float* __restrict__ out)                // [B][T][SD]
{
    __shared__ __align__(16) float scmd[WPB][T_STEPS * AD];   // whole cmd sequence per warp
    __shared__ __align__(16) float xbuf[WPB][16];             // dims 0..11 used (state part)
    __shared__ __align__(16) float hbuf[WPB][16];
    __shared__ ulonglong2 sWo[SD * 5];   // stride-5 quads: <=2-way bank conflict
    __shared__ float sbo[SD];

    int tid  = threadIdx.x;
    int w    = tid >> 5;     // warp in block = local batch
    int lane = tid & 31;
    int j    = lane & 15;
    int hi   = lane >> 4;
    int b    = blockIdx.x * WPB + w;

    // stage W_out into padded smem
    {
        const ulonglong2* gq = (const ulonglong2*)g_WoL;
        for (int i = tid; i < SD * 4; i += THREADS)
            sWo[(i >> 2) * 5 + (i & 3)] = gq[i];
        for (int i = tid; i < SD; i += THREADS) sbo[i] = g_boL[i];
    }
    // stage this batch's entire command sequence (coalesced, once)
    {
        const float4* cf = (const float4*)(commands + (size_t)b * (T_STEPS * AD));
        float4* sf = (float4*)scmd[w];
        #pragma unroll
        for (int i = 0; i < (T_STEPS * AD) / (4 * 32); i++)
            sf[lane + 32 * i] = cf[lane + 32 * i];
    }

    // loop-invariant gate weights in registers
    ull Wx[16], Wh[16];
    const ull* wx = (const ull*)g_WxL + lane * 16;
    const ull* wh = (const ull*)g_WhL + lane * 16;
    #pragma unroll
    for (int i = 0; i < 16; i++) { Wx[i] = wx[i]; Wh[i] = wh[i]; }
    float4 SB = g_SBL[lane];

    int  jw      = (j < SD) ? j : 0;
    bool stlane  = (hi == 0) && (j < SD);
    float kk2    = hi ? 0.5f : 1.0f;    // g1 pre-scale: sigmoid-via-tanh vs direct tanh

    float st = 0.f;
    if (stlane) st = init_state[b * SD + j];
    float c = 0.f;

    float* outp = out + (size_t)b * (T_STEPS * SD);

    // x(0) state part + h(-1) = 0
    if (stlane)  xbuf[w][j] = st;
    if (hi == 0) hbuf[w][j] = 0.f;
    __syncthreads();   // sWo + scmd + xbuf + hbuf visible

    const ulonglong2* xq4 = (const ulonglong2*)xbuf[w];
    const ulonglong2* hq4 = (const ulonglong2*)hbuf[w];
    const ulonglong2* cq4 = (const ulonglong2*)scmd[w];
    const ulonglong2* wop = sWo + jw * 5 + 2 * hi;    // this half's 2 Wout quads (split-K)
    const ulonglong2* hsel = hq4 + 2 * hi;            // this half's 2 h quads for Wout
    // b_out folded into accumulator init. Each half contributes bo/2 after its
    // horizontal sum, so the combined (aos + aoo) adds exactly bo once.
    ull bo2 = pk(sbo[jw] * 0.25f, sbo[jw] * 0.25f);

    int  p16 = (j >= 1 && j <= 6) ? (j + ((j & 1) ? 1 : -1)) : j;
    bool isc = (j >= 1 && j <= 6);

    #pragma unroll 4
    for (int t = 0; t < T_STEPS; t++) {
        // ---- x/h loads: batched (MLP), x quad 3 comes straight from staged cmds ----
        ulonglong2 v0 = xq4[0], v1 = xq4[1], v2 = xq4[2];
        ulonglong2 v3 = cq4[t];                       // cmd(t): dims 12..15, broadcast
        ulonglong2 h0 = hq4[0], h1 = hq4[1], h2 = hq4[2], h3 = hq4[3];
        ull xp[8], hp[8];
        xp[0] = v0.x; xp[1] = v0.y; xp[2] = v1.x; xp[3] = v1.y;
        xp[4] = v2.x; xp[5] = v2.y; xp[6] = v3.x; xp[7] = v3.y;
        hp[0] = h0.x; hp[1] = h0.y; hp[2] = h1.x; hp[3] = h1.y;
        hp[4] = h2.x; hp[5] = h2.y; hp[6] = h3.x; hp[7] = h3.y;

        // ---- LN stats (two chains) ----
        ull sa = xp[0], sb2 = xp[1];
        ull qa = mul2(xp[0], xp[0]), qb = mul2(xp[1], xp[1]);
        #pragma unroll
        for (int d = 2; d < 8; d += 2) {
            add2(sa, xp[d]);      fma2(qa, xp[d],     xp[d]);
            add2(sb2, xp[d + 1]); fma2(qb, xp[d + 1], xp[d + 1]);
        }
        add2(sa, sb2); add2(qa, qb);
        float2 su = up(sa), qu = up(qa);
        float mu   = (su.x + su.y) * 0.0625f;
        float var  = fmaf(-mu, mu, (qu.x + qu.y) * 0.0625f);
        float rstd = rsqrtf(var + 1e-5f);

        // ---- gate dots: x part + h part (h(t-1)) ----
        ull a0x = mul2(Wx[0], xp[0]);
        ull a1x = mul2(Wx[8], xp[0]);
        ull a0h = mul2(Wh[0], hp[0]);
        ull a1h = mul2(Wh[8], hp[0]);
        #pragma unroll
        for (int d = 1; d < 8; d++) {
            fma2(a0x, Wx[d],     xp[d]);
            fma2(a1x, Wx[8 + d], xp[d]);
            fma2(a0h, Wh[d],     hp[d]);
            fma2(a1h, Wh[8 + d], hp[d]);
        }
        float2 u0 = up(a0x), u1 = up(a1x), w0h = up(a0h), w1h = up(a1h);
        float g0 = fmaf(rstd, fmaf(-mu, SB.x, u0.x + u0.y), SB.z) + (w0h.x + w0h.y);
        float g1 = fmaf(rstd, fmaf(-mu, SB.y, u1.x + u1.y), SB.w) + (w1h.x + w1h.y);

        // ---- activations via MUFU.TANH ----
        // hi=0 lane: sA = sig(i), tb = tanh(g)
        // hi=1 lane: sA = sig(f), v1a = sig(o) = 0.5 + 0.5*tanh(g1/2)
        float sA = fmaf(0.5f, tanh_(g0 * 0.5f), 0.5f);
        float tb = tanh_(g1 * kk2);
        float v1a = hi ? fmaf(0.5f, tb, 0.5f) : tb;
        float a  = sA * v1a;                              // sig(i)*tanh(g) on hi=0
        float send1 = hi ? sA : a;
        float fs = __shfl_xor_sync(0xffffffffu, send1, 16);  // hi=0 gets sig(f)
        float os = __shfl_xor_sync(0xffffffffu, v1a, 16);    // hi=0 gets sig(o)
        c = fmaf(fs, c, a);
        float h = os * tanh_(c);

        if (hi == 0) hbuf[w][j] = h;
        __syncwarp();

        // ---- Wout split-K: this half dots its 8 dims of h(t) ----
        ulonglong2 hs0 = hsel[0], hs1 = hsel[1];
        ulonglong2 wv0 = wop[0],  wv1 = wop[1];
        ull ao = bo2;
        fma2(ao, wv0.x, hs0.x); fma2(ao, wv0.y, hs0.y);
        fma2(ao, wv1.x, hs1.x); fma2(ao, wv1.y, hs1.y);
        float2 aof = up(ao);
        float aos = aof.x + aof.y;
        float aoo = __shfl_xor_sync(0xffffffffu, aos, 16);
        st = st + (aos + aoo);

        // ---- sincos renorm, branch-free ----
        float other = __shfl_sync(0xffffffffu, st, p16, 16);
        float rn = rsqrtf(fmaf(st, st, other * other));
        st = isc ? st * rn : st;

        if (stlane) { outp[t * SD + j] = st; xbuf[w][j] = st; }
        __syncwarp();
    }
}

extern "C" void kernel_launch(void* const* d_in, const int* in_sizes, int n_in,
                              void* d_out, int out_size) {
    const float* init_state = (const float*)d_in[0];
    const float* commands   = (const float*)d_in[1];
    const float* ln_gamma   = (const float*)d_in[2];
    const float* ln_beta    = (const float*)d_in[3];
    const float* W_in       = (const float*)d_in[4];
    const float* b_in       = (const float*)d_in[5];
    const float* W_ih       = (const float*)d_in[6];
    const float* W_hh       = (const float*)d_in[7];
    const float* b_ih       = (const float*)d_in[8];
    const float* b_hh       = (const float*)d_in[9];
    const float* W_out      = (const float*)d_in[10];
    const float* b_out      = (const float*)d_in[11];
    float* out = (float*)d_out;

    vm_prep<<<1, 64>>>(ln_gamma, ln_beta, W_in, b_in, W_ih, W_hh, b_ih, b_hh, W_out, b_out);
    vm_main<<<NBLOCKS, THREADS>>>(init_state, commands, out);
}